// round 2
// baseline (speedup 1.0000x reference)
#include <cuda_runtime.h>
#include <math.h>

#define NQV   65536
#define NVV   1558
#define NUMVV 779

// scratch (no allocs allowed)
__device__ float g_A21[21*256*256];
__device__ float g_A42[42*256*256];
__device__ float g_B21[21*64*64];
__device__ float g_B42[42*64*64];
__device__ float g_mean[64];
__device__ float g_rstd[64];
__device__ float g_gf[42*18];
__device__ float g_H779[NUMVV*18];
__device__ float g_vf[NVV*29];
__device__ int   g_idx[NQV];

// ---------------- 3x3 conv pad1: block=128 thr = 16x8 px, all COUT per thread ----------------
template<int CIN, int COUT, int HW>
__global__ __launch_bounds__(128) void conv3x3(const float* __restrict__ in,
                                               const float* __restrict__ w,
                                               float* __restrict__ out)
{
    constexpr int CP = (COUT + 3) & ~3;
    extern __shared__ float sm[];
    float* sin_ = sm;               // CIN*10*18 halo tile
    float* swt  = sm + CIN * 180;   // transposed weights [CIN*9][CP]
    int tid = threadIdx.x;
    int bx = blockIdx.x * 16, by = blockIdx.y * 8;

    for (int i = tid; i < CIN * 180; i += 128) {
        int ci = i / 180, r = (i % 180) / 18, c = i % 18;
        int gy = by + r - 1, gx = bx + c - 1;
        float v = 0.f;
        if (gy >= 0 && gy < HW && gx >= 0 && gx < HW) v = in[ci * HW * HW + gy * HW + gx];
        sin_[i] = v;
    }
    for (int i = tid; i < CIN * 9 * CP; i += 128) {
        int kk = i / CP, co = i % CP;
        swt[i] = (co < COUT) ? w[co * CIN * 9 + kk] : 0.f;
    }
    __syncthreads();

    int px = tid & 15, py = tid >> 4;
    float acc[CP];
#pragma unroll
    for (int g = 0; g < CP; g++) acc[g] = 0.f;
    for (int ci = 0; ci < CIN; ci++) {
#pragma unroll
        for (int ky = 0; ky < 3; ky++)
#pragma unroll
        for (int kx = 0; kx < 3; kx++) {
            float v = sin_[ci * 180 + (py + ky) * 18 + px + kx];
            const float4* wr = (const float4*)(swt + (ci * 9 + ky * 3 + kx) * CP);
#pragma unroll
            for (int g = 0; g < CP / 4; g++) {
                float4 w4 = wr[g];
                acc[g*4+0] = fmaf(v, w4.x, acc[g*4+0]);
                acc[g*4+1] = fmaf(v, w4.y, acc[g*4+1]);
                acc[g*4+2] = fmaf(v, w4.z, acc[g*4+2]);
                acc[g*4+3] = fmaf(v, w4.w, acc[g*4+3]);
            }
        }
    }
    int ox = bx + px, oy = by + py;
#pragma unroll
    for (int co = 0; co < COUT; co++) out[co * HW * HW + oy * HW + ox] = acc[co];
}

// ---------------- per-channel mean/rstd over H*W ----------------
__global__ void chan_stats(const float* __restrict__ x, int N, float* mean, float* rstd)
{
    __shared__ float s1[256], s2[256];
    int c = blockIdx.x;
    const float* p = x + (size_t)c * N;
    float a = 0.f, b = 0.f;
    for (int i = threadIdx.x; i < N; i += 256) { float v = p[i]; a += v; b += v * v; }
    s1[threadIdx.x] = a; s2[threadIdx.x] = b;
    __syncthreads();
    for (int s = 128; s > 0; s >>= 1) {
        if (threadIdx.x < s) { s1[threadIdx.x] += s1[threadIdx.x+s]; s2[threadIdx.x] += s2[threadIdx.x+s]; }
        __syncthreads();
    }
    if (threadIdx.x == 0) {
        float m = s1[0] / (float)N;
        mean[c] = m;
        rstd[c] = rsqrtf(s2[0] / (float)N - m * m + 1e-6f);
    }
}

__global__ void ln_relu(float* __restrict__ x, const float* __restrict__ mean,
                        const float* __restrict__ rstd, const float* __restrict__ g,
                        const float* __restrict__ b, int N, int total)
{
    int i = blockIdx.x * 256 + threadIdx.x;
    if (i >= total) return;
    int c = i / N, p = i % N;
    x[i] = fmaxf((x[i] - mean[c]) * rstd[c] * g[p] + b[p], 0.f);
}

// ---------------- adaptive avg pool -> 3x3, writes gf[c][colbase + r] ----------------
__global__ void apool(const float* __restrict__ A, int HW, float* __restrict__ gf, int colbase)
{
    __shared__ float sred[256];
    int r = blockIdx.x, c = blockIdx.y;
    int ri = r / 3, rj = r % 3;
    int ylo = ri * HW / 3, yhi = ((ri + 1) * HW + 2) / 3;
    int xlo = rj * HW / 3, xhi = ((rj + 1) * HW + 2) / 3;
    int wl = xhi - xlo, cnt = (yhi - ylo) * wl;
    const float* p = A + (size_t)c * HW * HW;
    float s = 0.f;
    for (int i = threadIdx.x; i < cnt; i += 256) {
        int y = ylo + i / wl, x = xlo + i % wl;
        s += p[y * HW + x];
    }
    sred[threadIdx.x] = s;
    __syncthreads();
    for (int st = 128; st > 0; st >>= 1) {
        if (threadIdx.x < st) sred[threadIdx.x] += sred[threadIdx.x + st];
        __syncthreads();
    }
    if (threadIdx.x == 0) gf[c * 18 + colbase + r] = sred[0] / (float)cnt;
}

__device__ __forceinline__ float wsum(float v)
{
#pragma unroll
    for (int o = 16; o > 0; o >>= 1) v += __shfl_xor_sync(0xffffffffu, v, o);
    return v;
}

// ---------------- gt1: conv1d3 42->779 len18, LN(18)+relu. 1 warp/out-channel ----------------
__global__ void gt1_k(const float* __restrict__ gf, const float* __restrict__ w,
                      const float* __restrict__ g, const float* __restrict__ b,
                      float* __restrict__ out)
{
    __shared__ float s[42 * 18];
    int o = blockIdx.x, t = threadIdx.x;
    for (int i = t; i < 42 * 18; i += 32) s[i] = gf[i];
    __syncthreads();
    float acc = 0.f;
    if (t < 18) {
        const float* wo = w + o * 126;
        for (int c = 0; c < 42; c++) {
#pragma unroll
            for (int k = 0; k < 3; k++) {
                int tt = t + k - 1;
                if (tt >= 0 && tt < 18) acc = fmaf(s[c * 18 + tt], wo[c * 3 + k], acc);
            }
        }
    }
    float v  = (t < 18) ? acc : 0.f;
    float m  = wsum(v) / 18.f;
    float sq = wsum(v * v) / 18.f;
    float rs = rsqrtf(sq - m * m + 1e-6f);
    if (t < 18) out[o * 18 + t] = fmaxf((acc - m) * rs * g[t] + b[t], 0.f);
}

// ---------------- gt2: conv1d3 779->1558 len18, LN(18)+relu -> vf[:,11:29] ----------------
__global__ __launch_bounds__(256) void gt2_k(const float* __restrict__ h,
                                             const float* __restrict__ w,
                                             const float* __restrict__ g,
                                             const float* __restrict__ b,
                                             float* __restrict__ vf)
{
    extern __shared__ float sm[];
    float* Hs  = sm;               // 779*19
    float* red = sm + 779 * 19;    // 256*18
    int o = blockIdx.x, tid = threadIdx.x;
    for (int i = tid; i < 779 * 18; i += 256) Hs[(i / 18) * 19 + (i % 18)] = h[i];
    __syncthreads();
    float acc[18];
#pragma unroll
    for (int t = 0; t < 18; t++) acc[t] = 0.f;
    for (int c = tid; c < 779; c += 256) {
        const float* wc = w + (size_t)o * 2337 + c * 3;
        float w0 = wc[0], w1 = wc[1], w2 = wc[2];
        const float* hc = Hs + c * 19;
        float hv[20];
        hv[0] = 0.f; hv[19] = 0.f;
#pragma unroll
        for (int t = 0; t < 18; t++) hv[t + 1] = hc[t];
#pragma unroll
        for (int t = 0; t < 18; t++)
            acc[t] += w0 * hv[t] + w1 * hv[t + 1] + w2 * hv[t + 2];
    }
#pragma unroll
    for (int t = 0; t < 18; t++) red[tid * 18 + t] = acc[t];
    __syncthreads();
    for (int s = 128; s > 0; s >>= 1) {
        if (tid < s)
#pragma unroll
            for (int t = 0; t < 18; t++) red[tid * 18 + t] += red[(tid + s) * 18 + t];
        __syncthreads();
    }
    if (tid < 32) {
        float a  = (tid < 18) ? red[tid] : 0.f;
        float m  = wsum(a) / 18.f;
        float sq = wsum(a * a) / 18.f;
        float rs = rsqrtf(sq - m * m + 1e-6f);
        if (tid < 18) vf[o * 29 + 11 + tid] = fmaxf((a - m) * rs * g[tid] + b[tid], 0.f);
    }
}

// ---------------- bilinear vertex sampling -> vf[:,0:11] ----------------
__device__ __forceinline__ void bsetup(float c, int L, int& i0, int& i1, float& w)
{
    float xs = (c + 1.f) * 0.5f * (float)(L - 1);
    float f = floorf(xs);
    w = xs - f;
    int a = (int)f;
    i0 = min(max(a, 0), L - 1);
    i1 = min(max(a + 1, 0), L - 1);
}

__global__ void feat_vert_k(const float* __restrict__ vxy, const float* __restrict__ img,
                            const float* __restrict__ ft, float* __restrict__ vf)
{
    int p = blockIdx.x * 256 + threadIdx.x;
    if (p >= NVV) return;
    float xc = vxy[p * 2], yc = vxy[p * 2 + 1];
    int x0, x1, y0, y1; float wx, wy;
    bsetup(xc, 256, x0, x1, wx); bsetup(yc, 256, y0, y1, wy);
#pragma unroll
    for (int c = 0; c < 3; c++) {
        const float* f = img + c * 65536;
        float v00=f[y0*256+x0], v01=f[y0*256+x1], v10=f[y1*256+x0], v11=f[y1*256+x1];
        vf[p*29+c] = v00*(1.f-wx)*(1.f-wy) + v01*wx*(1.f-wy) + v10*(1.f-wx)*wy + v11*wx*wy;
    }
    bsetup(xc, 64, x0, x1, wx); bsetup(yc, 64, y0, y1, wy);
#pragma unroll
    for (int c = 0; c < 8; c++) {
        const float* f = ft + c * 4096;
        float v00=f[y0*64+x0], v01=f[y0*64+x1], v10=f[y1*64+x0], v11=f[y1*64+x1];
        vf[p*29+3+c] = v00*(1.f-wx)*(1.f-wy) + v01*wx*(1.f-wy) + v10*(1.f-wx)*wy + v11*wx*wy;
    }
}

// ---------------- nearest-vertex argmin ----------------
__global__ __launch_bounds__(256) void argmin_k(const float* __restrict__ v,
                                                const float* __restrict__ vert,
                                                int* __restrict__ idx)
{
    __shared__ float sx[NVV], sy[NVV], sz[NVV], s2[NVV];
    int tid = threadIdx.x;
    for (int i = tid; i < NVV; i += 256) {
        float x = vert[i*3], y = vert[i*3+1], z = vert[i*3+2];
        sx[i] = x; sy[i] = y; sz[i] = z; s2[i] = x*x + y*y + z*z;
    }
    __syncthreads();
    int q = blockIdx.x * 256 + tid;
    float qx = v[q*3], qy = v[q*3+1], qz = v[q*3+2];
    float best = 3.4e38f; int bi = 0;
    for (int p = 0; p < NVV; p++) {
        float d = s2[p] - 2.f * (qx*sx[p] + qy*sy[p] + qz*sz[p]);
        if (d < best) { best = d; bi = p; }
    }
    idx[q] = bi;
}

// ---------------- fused per-query MLP stack ----------------
#define QT 128

__device__ __forceinline__ void gemm_relu(const float* __restrict__ A,
                                          const float* __restrict__ W,
                                          float* __restrict__ C, int tid)
{
    int q0 = (tid >> 4) << 2;      // 0..124
    int t16 = tid & 15;            // o = t16 + 16*j
    float acc[4][6];
#pragma unroll
    for (int i = 0; i < 4; i++)
#pragma unroll
        for (int j = 0; j < 6; j++) acc[i][j] = 0.f;
#pragma unroll 4
    for (int k = 0; k < 96; k += 4) {
        float4 a[4], w4[6];
#pragma unroll
        for (int i = 0; i < 4; i++) a[i] = *(const float4*)(A + (q0 + i) * 100 + k);
#pragma unroll
        for (int j = 0; j < 6; j++) w4[j] = *(const float4*)(W + (t16 + 16 * j) * 100 + k);
#pragma unroll
        for (int i = 0; i < 4; i++)
#pragma unroll
            for (int j = 0; j < 6; j++) {
                acc[i][j] = fmaf(a[i].x, w4[j].x, acc[i][j]);
                acc[i][j] = fmaf(a[i].y, w4[j].y, acc[i][j]);
                acc[i][j] = fmaf(a[i].z, w4[j].z, acc[i][j]);
                acc[i][j] = fmaf(a[i].w, w4[j].w, acc[i][j]);
            }
    }
#pragma unroll
    for (int i = 0; i < 4; i++)
#pragma unroll
        for (int j = 0; j < 6; j++)
            C[(q0 + i) * 100 + t16 + 16 * j] = fmaxf(acc[i][j], 0.f);
}

__global__ __launch_bounds__(512) void fused_main(
    const float* __restrict__ img_xy, const float* __restrict__ ft_xy,
    const float* __restrict__ latent, const float* __restrict__ qvis,
    const float* __restrict__ vvis,
    const float* __restrict__ at_w1, const float* __restrict__ at_w2,
    const float* __restrict__ fw1, const float* __restrict__ fw2,
    float* __restrict__ out)
{
    extern __shared__ float sm[];
    float* w1s = sm;              // 96x100
    float* f1s = w1s + 9600;      // 96x100
    float* f2s = f1s + 9600;      // 40x100
    float* w2s = f2s + 4000;      // 6x96
    float* Ys  = w2s + 576;       // 128x100
    float* Hs  = Ys + 12800;      // 128x100
    float* ATs = Hs + 12800;      // 128x6
    int tid = threadIdx.x;

    for (int i = tid; i < 9216; i += 512) {
        int o = i / 96, c = i % 96;
        w1s[o * 100 + c] = at_w1[i];
        f1s[o * 100 + c] = fw1[i];
    }
    for (int i = tid; i < 40 * 96; i += 512) f2s[(i / 96) * 100 + (i % 96)] = fw2[i];
    for (int i = tid; i < 576; i += 512) w2s[i] = at_w2[i];

    int qb = blockIdx.x * QT;
    for (int e = tid; e < QT * 96; e += 512) {
        int q = e / 96, c = e % 96, gq = qb + q;
        float val;
        if (c < 3) val = img_xy[gq * 3 + c];
        else if (c < 11) val = ft_xy[gq * 8 + (c - 3)];
        else if (c < 69) {
            int i0 = g_idx[gq];
            int i1 = i0 + NUMVV; if (i1 >= NVV) i1 -= NVV;
            if (c < 22)      val = g_vf[i0 * 29 + (c - 11)]      * vvis[i0];
            else if (c < 33) val = g_vf[i1 * 29 + (c - 22)]      * vvis[i1];
            else if (c < 51) val = g_vf[i0 * 29 + 11 + (c - 33)] * vvis[i0];
            else             val = g_vf[i1 * 29 + 11 + (c - 51)] * vvis[i1];
        }
        else if (c < 93) val = latent[gq * 24 + (c - 69)];
        else if (c == 93) val = qvis[gq];
        else {
            int i0 = g_idx[gq];
            if (c == 94) val = vvis[i0];
            else { int i1 = i0 + NUMVV; if (i1 >= NVV) i1 -= NVV; val = vvis[i1]; }
        }
        Ys[q * 100 + c] = val;
    }
    __syncthreads();

    gemm_relu(Ys, w1s, Hs, tid);            // h1 = relu(at_w1 @ y)
    __syncthreads();

    for (int e = tid; e < QT * 6; e += 512) {   // at = sigmoid(at_w2 @ h1)
        int q = e / 6, o = e % 6;
        const float4* wp = (const float4*)(w2s + o * 96);
        const float4* hp = (const float4*)(Hs + q * 100);
        float s = 0.f;
#pragma unroll
        for (int k = 0; k < 24; k++) {
            float4 a = wp[k], b = hp[k];
            s += a.x*b.x + a.y*b.y + a.z*b.z + a.w*b.w;
        }
        ATs[e] = 1.f / (1.f + expf(-s));
    }
    __syncthreads();

    for (int e = tid; e < QT * 96; e += 512) {  // y2: scale sections
        int q = e / 96, c = e % 96;
        int s = (c < 11) ? 0 : (c < 22) ? 1 : (c < 33) ? 2 : (c < 51) ? 3 : (c < 69) ? 4 : (c < 93) ? 5 : -1;
        if (s >= 0) Ys[q * 100 + c] *= ATs[q * 6 + s];
    }
    __syncthreads();

    gemm_relu(Ys, f1s, Hs, tid);            // h2 = relu(fconv_w1 @ y2)
    __syncthreads();

    for (int e = tid; e < QT * 40; e += 512) {  // out = fconv_w2 @ h2
        int q = e / 40, o = e % 40;
        const float4* wp = (const float4*)(f2s + o * 100);
        const float4* hp = (const float4*)(Hs + q * 100);
        float s = 0.f;
#pragma unroll
        for (int k = 0; k < 24; k++) {
            float4 a = wp[k], b = hp[k];
            s += a.x*b.x + a.y*b.y + a.z*b.z + a.w*b.w;
        }
        out[(size_t)(qb + q) * 40 + o] = s;
    }
}

extern "C" void kernel_launch(void* const* d_in, const int* in_sizes, int n_in,
                              void* d_out, int out_size)
{
    const float* vert_xy = (const float*)d_in[0];
    const float* ft1     = (const float*)d_in[1];
    const float* ft_xy   = (const float*)d_in[2];
    const float* vert    = (const float*)d_in[3];
    const float* v       = (const float*)d_in[4];
    const float* vvis    = (const float*)d_in[5];
    const float* qvis    = (const float*)d_in[6];
    const float* img_xy  = (const float*)d_in[7];
    const float* img     = (const float*)d_in[8];
    const float* latent  = (const float*)d_in[9];
    const float* fw1     = (const float*)d_in[10];
    const float* fw2     = (const float*)d_in[11];
    const float* at_w1   = (const float*)d_in[12];
    const float* at_w2   = (const float*)d_in[13];
    const float* gt_w1   = (const float*)d_in[14];
    const float* gt_g1   = (const float*)d_in[15];
    const float* gt_b1   = (const float*)d_in[16];
    const float* gt_w2   = (const float*)d_in[17];
    const float* gt_g2   = (const float*)d_in[18];
    const float* gt_b2   = (const float*)d_in[19];
    const float* c3_w1   = (const float*)d_in[20];
    const float* c3_g1   = (const float*)d_in[21];
    const float* c3_b1   = (const float*)d_in[22];
    const float* c3_w2   = (const float*)d_in[23];
    const float* c3_g2   = (const float*)d_in[24];
    const float* c3_b2   = (const float*)d_in[25];
    const float* c4_w1   = (const float*)d_in[26];
    const float* c4_g1   = (const float*)d_in[27];
    const float* c4_b1   = (const float*)d_in[28];
    const float* c4_w2   = (const float*)d_in[29];
    const float* c4_g2   = (const float*)d_in[30];
    const float* c4_b2   = (const float*)d_in[31];
    float* out = (float*)d_out;

    float *A21, *A42, *B21, *B42, *mean, *rstd, *gf, *H779, *vf;
    int* idx;
    cudaGetSymbolAddress((void**)&A21,  g_A21);
    cudaGetSymbolAddress((void**)&A42,  g_A42);
    cudaGetSymbolAddress((void**)&B21,  g_B21);
    cudaGetSymbolAddress((void**)&B42,  g_B42);
    cudaGetSymbolAddress((void**)&mean, g_mean);
    cudaGetSymbolAddress((void**)&rstd, g_rstd);
    cudaGetSymbolAddress((void**)&gf,   g_gf);
    cudaGetSymbolAddress((void**)&H779, g_H779);
    cudaGetSymbolAddress((void**)&vf,   g_vf);
    cudaGetSymbolAddress((void**)&idx,  g_idx);

    static bool attr_done = false;
    if (!attr_done) {
        cudaFuncSetAttribute(gt2_k, cudaFuncAttributeMaxDynamicSharedMemorySize, (779*19 + 256*18) * 4);
        cudaFuncSetAttribute(fused_main, cudaFuncAttributeMaxDynamicSharedMemorySize, 50144 * 4);
        attr_done = true;
    }

    // vertex feature sampling (vf[:,0:11])
    feat_vert_k<<<(NVV + 255) / 256, 256>>>(vert_xy, img, ft1, vf);

    // c4 branch: img_fmap 256x256
    conv3x3<3, 21, 256><<<dim3(16, 32), 128, (3*180 + 3*9*24) * 4>>>(img, c4_w1, A21);
    chan_stats<<<21, 256>>>(A21, 65536, mean, rstd);
    ln_relu<<<(21 * 65536) / 256, 256>>>(A21, mean, rstd, c4_g1, c4_b1, 65536, 21 * 65536);
    conv3x3<21, 42, 256><<<dim3(16, 32), 128, (21*180 + 21*9*44) * 4>>>(A21, c4_w2, A42);
    chan_stats<<<42, 256>>>(A42, 65536, mean, rstd);
    ln_relu<<<(42 * 65536) / 256, 256>>>(A42, mean, rstd, c4_g2, c4_b2, 65536, 42 * 65536);
    apool<<<dim3(9, 42), 256>>>(A42, 256, gf, 0);

    // c3 branch: ft1 64x64
    conv3x3<8, 21, 64><<<dim3(4, 8), 128, (8*180 + 8*9*24) * 4>>>(ft1, c3_w1, B21);
    chan_stats<<<21, 256>>>(B21, 4096, mean, rstd);
    ln_relu<<<(21 * 4096) / 256, 256>>>(B21, mean, rstd, c3_g1, c3_b1, 4096, 21 * 4096);
    conv3x3<21, 42, 64><<<dim3(4, 8), 128, (21*180 + 21*9*44) * 4>>>(B21, c3_w2, B42);
    chan_stats<<<42, 256>>>(B42, 4096, mean, rstd);
    ln_relu<<<(42 * 4096) / 256, 256>>>(B42, mean, rstd, c3_g2, c3_b2, 4096, 42 * 4096);
    apool<<<dim3(9, 42), 256>>>(B42, 64, gf, 9);

    // graph convs
    gt1_k<<<NUMVV, 32>>>(gf, gt_w1, gt_g1, gt_b1, H779);
    gt2_k<<<NVV, 256, (779*19 + 256*18) * 4>>>(H779, gt_w2, gt_g2, gt_b2, vf);

    // nearest vertex
    argmin_k<<<NQV / 256, 256>>>(v, vert, idx);

    // fused MLP stack
    fused_main<<<NQV / QT, 512, 50144 * 4>>>(img_xy, ft_xy, latent, qvis, vvis,
                                             at_w1, at_w2, fw1, fw2, out);
}

// round 3
// speedup vs baseline: 1.2381x; 1.2381x over previous
#include <cuda_runtime.h>
#include <math.h>

#define NQV   65536
#define NVV   1558
#define NUMVV 779

typedef unsigned long long ull;

__device__ __forceinline__ ull pack2(float lo, float hi) {
    ull r; asm("mov.b64 %0,{%1,%2};" : "=l"(r) : "f"(lo), "f"(hi)); return r;
}
__device__ __forceinline__ float2 unpk(ull v) {
    float2 r; asm("mov.b64 {%0,%1},%2;" : "=f"(r.x), "=f"(r.y) : "l"(v)); return r;
}
__device__ __forceinline__ ull ffma2(ull a, ull b, ull c) {
    ull d; asm("fma.rn.f32x2 %0,%1,%2,%3;" : "=l"(d) : "l"(a), "l"(b), "l"(c)); return d;
}
__device__ __forceinline__ ull fmul2(ull a, ull b) {
    ull d; asm("mul.rn.f32x2 %0,%1,%2;" : "=l"(d) : "l"(a), "l"(b)); return d;
}

// scratch
__device__ float g_A21[21*256*256];
__device__ float g_A42[42*256*256];
__device__ float g_B21[21*64*64];
__device__ float g_B42[42*64*64];
__device__ float g_meanA[64];
__device__ float g_rstdA[64];
__device__ float g_meanB[64];
__device__ float g_rstdB[64];
__device__ float g_gf[42*18];
__device__ float g_H779[NUMVV*18];
__device__ float g_vf[NVV*29];
__device__ int   g_idx[NQV];

// ---------------- 3x3 conv pad1, f32x2 channel pairs, optional fused LN+relu on input ----------------
template<int CIN, int COUT, int HW, bool FLN>
__global__ __launch_bounds__(128) void conv3x3(const float* __restrict__ in,
                                               const float* __restrict__ w,
                                               float* __restrict__ out,
                                               const float* __restrict__ mean,
                                               const float* __restrict__ rstd,
                                               const float* __restrict__ lng,
                                               const float* __restrict__ lnb)
{
    constexpr int NP  = (COUT + 1) / 2;
    constexpr int NPP = NP + (NP & 1);
    extern __shared__ float sm[];
    float* sin_ = sm;                         // CIN*10*18 halo tile
    ull*   swt  = (ull*)(sm + CIN * 180);     // [CIN*9][NPP] packed channel pairs
    int tid = threadIdx.x;
    int bx = blockIdx.x * 16, by = blockIdx.y * 8;

    for (int i = tid; i < CIN * 180; i += 128) {
        int ci = i / 180, r = (i % 180) / 18, c = i % 18;
        int gy = by + r - 1, gx = bx + c - 1;
        float v = 0.f;
        if (gy >= 0 && gy < HW && gx >= 0 && gx < HW) {
            v = in[ci * HW * HW + gy * HW + gx];
            if (FLN) {
                int pix = gy * HW + gx;
                v = fmaxf((v - mean[ci]) * rstd[ci] * lng[pix] + lnb[pix], 0.f);
            }
        }
        sin_[i] = v;
    }
    for (int i = tid; i < CIN * 9 * NPP; i += 128) {
        int kk = i / NPP, p = i % NPP;
        float lo = (2*p   < COUT) ? w[(2*p)   * CIN * 9 + kk] : 0.f;
        float hi = (2*p+1 < COUT) ? w[(2*p+1) * CIN * 9 + kk] : 0.f;
        swt[i] = pack2(lo, hi);
    }
    __syncthreads();

    int px = tid & 15, py = tid >> 4;
    ull acc[NPP];
#pragma unroll
    for (int p = 0; p < NPP; p++) acc[p] = 0ull;

    for (int ci = 0; ci < CIN; ci++) {
#pragma unroll
        for (int ky = 0; ky < 3; ky++)
#pragma unroll
        for (int kx = 0; kx < 3; kx++) {
            float v = sin_[ci * 180 + (py + ky) * 18 + px + kx];
            ull vd = pack2(v, v);
            const ull* wr = swt + (ci * 9 + ky * 3 + kx) * NPP;
#pragma unroll
            for (int p = 0; p < NPP; p += 2) {
                ulonglong2 wp = *(const ulonglong2*)(wr + p);
                acc[p]   = ffma2(vd, wp.x, acc[p]);
                acc[p+1] = ffma2(vd, wp.y, acc[p+1]);
            }
        }
    }
    int ox = bx + px, oy = by + py;
#pragma unroll
    for (int p = 0; p < NP; p++) {
        float2 r = unpk(acc[p]);
        out[(2*p) * HW * HW + oy * HW + ox] = r.x;
        if (2*p+1 < COUT) out[(2*p+1) * HW * HW + oy * HW + ox] = r.y;
    }
}

// ---------------- per-channel mean/rstd over H*W ----------------
__global__ void chan_stats(const float* __restrict__ x, int N, float* mean, float* rstd)
{
    __shared__ float s1[256], s2[256];
    int c = blockIdx.x;
    const float* p = x + (size_t)c * N;
    float a = 0.f, b = 0.f;
    for (int i = threadIdx.x; i < N; i += 256) { float v = p[i]; a += v; b += v * v; }
    s1[threadIdx.x] = a; s2[threadIdx.x] = b;
    __syncthreads();
    for (int s = 128; s > 0; s >>= 1) {
        if (threadIdx.x < s) { s1[threadIdx.x] += s1[threadIdx.x+s]; s2[threadIdx.x] += s2[threadIdx.x+s]; }
        __syncthreads();
    }
    if (threadIdx.x == 0) {
        float m = s1[0] / (float)N;
        mean[c] = m;
        rstd[c] = rsqrtf(s2[0] / (float)N - m * m + 1e-6f);
    }
}

// ---------------- adaptive avg pool -> 3x3 with fused LN+relu ----------------
__global__ void apool(const float* __restrict__ A, int HW,
                      const float* __restrict__ mean, const float* __restrict__ rstd,
                      const float* __restrict__ lng,  const float* __restrict__ lnb,
                      float* __restrict__ gf, int colbase)
{
    __shared__ float sred[256];
    int r = blockIdx.x, c = blockIdx.y;
    int ri = r / 3, rj = r % 3;
    int ylo = ri * HW / 3, yhi = ((ri + 1) * HW + 2) / 3;
    int xlo = rj * HW / 3, xhi = ((rj + 1) * HW + 2) / 3;
    int wl = xhi - xlo, cnt = (yhi - ylo) * wl;
    const float* base = A + (size_t)c * HW * HW;
    float m = mean[c], rs = rstd[c];
    float s = 0.f;
    for (int i = threadIdx.x; i < cnt; i += 256) {
        int y = ylo + i / wl, x = xlo + i % wl;
        int pix = y * HW + x;
        float v = fmaxf((base[pix] - m) * rs * lng[pix] + lnb[pix], 0.f);
        s += v;
    }
    sred[threadIdx.x] = s;
    __syncthreads();
    for (int st = 128; st > 0; st >>= 1) {
        if (threadIdx.x < st) sred[threadIdx.x] += sred[threadIdx.x + st];
        __syncthreads();
    }
    if (threadIdx.x == 0) gf[c * 18 + colbase + r] = sred[0] / (float)cnt;
}

__device__ __forceinline__ float wsum(float v)
{
#pragma unroll
    for (int o = 16; o > 0; o >>= 1) v += __shfl_xor_sync(0xffffffffu, v, o);
    return v;
}

// ---------------- gt1: conv1d3 42->779 len18, LN(18)+relu ----------------
__global__ void gt1_k(const float* __restrict__ gf, const float* __restrict__ w,
                      const float* __restrict__ g, const float* __restrict__ b,
                      float* __restrict__ out)
{
    __shared__ float s[42 * 18];
    int o = blockIdx.x, t = threadIdx.x;
    for (int i = t; i < 42 * 18; i += 32) s[i] = gf[i];
    __syncthreads();
    float acc = 0.f;
    if (t < 18) {
        const float* wo = w + o * 126;
        for (int c = 0; c < 42; c++) {
#pragma unroll
            for (int k = 0; k < 3; k++) {
                int tt = t + k - 1;
                if (tt >= 0 && tt < 18) acc = fmaf(s[c * 18 + tt], wo[c * 3 + k], acc);
            }
        }
    }
    float v  = (t < 18) ? acc : 0.f;
    float m  = wsum(v) / 18.f;
    float sq = wsum(v * v) / 18.f;
    float rs = rsqrtf(sq - m * m + 1e-6f);
    if (t < 18) out[o * 18 + t] = fmaxf((acc - m) * rs * g[t] + b[t], 0.f);
}

// ---------------- gt2: conv1d3 779->1558 len18, LN(18)+relu -> vf[:,11:29] ----------------
__global__ __launch_bounds__(256) void gt2_k(const float* __restrict__ h,
                                             const float* __restrict__ w,
                                             const float* __restrict__ g,
                                             const float* __restrict__ b,
                                             float* __restrict__ vf)
{
    extern __shared__ float sm[];
    float* Hs  = sm;               // 779*19
    float* red = sm + 779 * 19;    // 256*18
    int o = blockIdx.x, tid = threadIdx.x;
    for (int i = tid; i < 779 * 18; i += 256) Hs[(i / 18) * 19 + (i % 18)] = h[i];
    __syncthreads();
    float acc[18];
#pragma unroll
    for (int t = 0; t < 18; t++) acc[t] = 0.f;
    for (int c = tid; c < 779; c += 256) {
        const float* wc = w + (size_t)o * 2337 + c * 3;
        float w0 = wc[0], w1 = wc[1], w2 = wc[2];
        const float* hc = Hs + c * 19;
        float hv[20];
        hv[0] = 0.f; hv[19] = 0.f;
#pragma unroll
        for (int t = 0; t < 18; t++) hv[t + 1] = hc[t];
#pragma unroll
        for (int t = 0; t < 18; t++)
            acc[t] += w0 * hv[t] + w1 * hv[t + 1] + w2 * hv[t + 2];
    }
#pragma unroll
    for (int t = 0; t < 18; t++) red[tid * 18 + t] = acc[t];
    __syncthreads();
    for (int s = 128; s > 0; s >>= 1) {
        if (tid < s)
#pragma unroll
            for (int t = 0; t < 18; t++) red[tid * 18 + t] += red[(tid + s) * 18 + t];
        __syncthreads();
    }
    if (tid < 32) {
        float a  = (tid < 18) ? red[tid] : 0.f;
        float m  = wsum(a) / 18.f;
        float sq = wsum(a * a) / 18.f;
        float rs = rsqrtf(sq - m * m + 1e-6f);
        if (tid < 18) vf[o * 29 + 11 + tid] = fmaxf((a - m) * rs * g[tid] + b[tid], 0.f);
    }
}

// ---------------- bilinear vertex sampling -> vf[:,0:11] ----------------
__device__ __forceinline__ void bsetup(float c, int L, int& i0, int& i1, float& w)
{
    float xs = (c + 1.f) * 0.5f * (float)(L - 1);
    float f = floorf(xs);
    w = xs - f;
    int a = (int)f;
    i0 = min(max(a, 0), L - 1);
    i1 = min(max(a + 1, 0), L - 1);
}

__global__ void feat_vert_k(const float* __restrict__ vxy, const float* __restrict__ img,
                            const float* __restrict__ ft, float* __restrict__ vf)
{
    int p = blockIdx.x * 256 + threadIdx.x;
    if (p >= NVV) return;
    float xc = vxy[p * 2], yc = vxy[p * 2 + 1];
    int x0, x1, y0, y1; float wx, wy;
    bsetup(xc, 256, x0, x1, wx); bsetup(yc, 256, y0, y1, wy);
#pragma unroll
    for (int c = 0; c < 3; c++) {
        const float* f = img + c * 65536;
        float v00=f[y0*256+x0], v01=f[y0*256+x1], v10=f[y1*256+x0], v11=f[y1*256+x1];
        vf[p*29+c] = v00*(1.f-wx)*(1.f-wy) + v01*wx*(1.f-wy) + v10*(1.f-wx)*wy + v11*wx*wy;
    }
    bsetup(xc, 64, x0, x1, wx); bsetup(yc, 64, y0, y1, wy);
#pragma unroll
    for (int c = 0; c < 8; c++) {
        const float* f = ft + c * 4096;
        float v00=f[y0*64+x0], v01=f[y0*64+x1], v10=f[y1*64+x0], v11=f[y1*64+x1];
        vf[p*29+3+c] = v00*(1.f-wx)*(1.f-wy) + v01*wx*(1.f-wy) + v10*(1.f-wx)*wy + v11*wx*wy;
    }
}

// ---------------- nearest-vertex argmin, f32x2 pairs ----------------
__global__ __launch_bounds__(256) void argmin_k(const float* __restrict__ v,
                                                const float* __restrict__ vert,
                                                int* __restrict__ idx)
{
    __shared__ __align__(16) float sx[NVV];
    __shared__ __align__(16) float sy[NVV];
    __shared__ __align__(16) float sz[NVV];
    __shared__ __align__(16) float s2[NVV];
    int tid = threadIdx.x;
    for (int i = tid; i < NVV; i += 256) {
        float x = vert[i*3], y = vert[i*3+1], z = vert[i*3+2];
        sx[i] = x; sy[i] = y; sz[i] = z; s2[i] = x*x + y*y + z*z;
    }
    __syncthreads();
    int q = blockIdx.x * 256 + tid;
    float qx = v[q*3], qy = v[q*3+1], qz = v[q*3+2];
    ull qx2 = pack2(qx, qx), qy2 = pack2(qy, qy), qz2 = pack2(qz, qz);
    ull m2  = pack2(-2.f, -2.f);
    float best = 3.4e38f; int bi = 0;
    for (int p = 0; p < NVV; p += 2) {
        ull x2 = *(const ull*)(sx + p);
        ull y2 = *(const ull*)(sy + p);
        ull z2 = *(const ull*)(sz + p);
        ull s22 = *(const ull*)(s2 + p);
        ull dot = ffma2(x2, qx2, ffma2(y2, qy2, fmul2(z2, qz2)));
        ull d2  = ffma2(dot, m2, s22);
        float2 dd = unpk(d2);
        if (dd.x < best) { best = dd.x; bi = p; }
        if (dd.y < best) { best = dd.y; bi = p + 1; }
    }
    idx[q] = bi;
}

// ---------------- fused per-query MLP stack (f32x2 GEMMs) ----------------
#define QT 128
#define FM_SMEM 199040

__device__ __forceinline__ void gemm_relu2(const float* __restrict__ A,
                                           const ull* __restrict__ W,
                                           float* __restrict__ C, int tid)
{
    int q0 = (tid >> 4) << 2;
    int t16 = tid & 15;
    ull acc[4][3];
#pragma unroll
    for (int i = 0; i < 4; i++)
#pragma unroll
        for (int j = 0; j < 3; j++) acc[i][j] = 0ull;
#pragma unroll 2
    for (int ks = 0; ks < 96; ks += 4) {
        float4 a4[4];
#pragma unroll
        for (int i = 0; i < 4; i++) a4[i] = *(const float4*)(A + (q0 + i) * 100 + ks);
        ull w[3][4];
#pragma unroll
        for (int j = 0; j < 3; j++) {
            const ulonglong2* wp = (const ulonglong2*)(W + (t16 + 16 * j) * 98 + ks);
            ulonglong2 u0 = wp[0], u1 = wp[1];
            w[j][0] = u0.x; w[j][1] = u0.y; w[j][2] = u1.x; w[j][3] = u1.y;
        }
#pragma unroll
        for (int i = 0; i < 4; i++) {
            ull ax = pack2(a4[i].x, a4[i].x), ay = pack2(a4[i].y, a4[i].y);
            ull az = pack2(a4[i].z, a4[i].z), aw = pack2(a4[i].w, a4[i].w);
#pragma unroll
            for (int j = 0; j < 3; j++) {
                acc[i][j] = ffma2(ax, w[j][0], acc[i][j]);
                acc[i][j] = ffma2(ay, w[j][1], acc[i][j]);
                acc[i][j] = ffma2(az, w[j][2], acc[i][j]);
                acc[i][j] = ffma2(aw, w[j][3], acc[i][j]);
            }
        }
    }
#pragma unroll
    for (int i = 0; i < 4; i++)
#pragma unroll
        for (int j = 0; j < 3; j++) {
            float2 r = unpk(acc[i][j]);
            float2 o;
            o.x = fmaxf(r.x, 0.f);
            o.y = fmaxf(r.y, 0.f);
            *(float2*)(C + (q0 + i) * 100 + 2 * (t16 + 16 * j)) = o;
        }
}

__global__ __launch_bounds__(512) void fused_main(
    const float* __restrict__ img_xy, const float* __restrict__ ft_xy,
    const float* __restrict__ latent, const float* __restrict__ qvis,
    const float* __restrict__ vvis,
    const float* __restrict__ at_w1, const float* __restrict__ at_w2,
    const float* __restrict__ fw1, const float* __restrict__ fw2,
    float* __restrict__ out)
{
    extern __shared__ char smc[];
    ull*   uW1 = (ull*)smc;                 // 48 x 98 packed pairs of at_w1
    ull*   uF1 = uW1 + 4704;                // 48 x 98 packed pairs of fconv_w1
    float* f2s = (float*)(uF1 + 4704);      // 40 x 100
    float* w2s = f2s + 4000;                // 6 x 96
    float* Ys  = w2s + 576;                 // 128 x 100
    float* Hs  = Ys + 12800;                // 128 x 100
    float* ATs = Hs + 12800;                // 128 x 6
    int tid = threadIdx.x;

    for (int i = tid; i < 48 * 96; i += 512) {
        int op = i / 96, k = i % 96;
        uW1[op * 98 + k] = pack2(at_w1[(2*op) * 96 + k], at_w1[(2*op+1) * 96 + k]);
        uF1[op * 98 + k] = pack2(fw1[(2*op) * 96 + k],   fw1[(2*op+1) * 96 + k]);
    }
    for (int i = tid; i < 40 * 96; i += 512) f2s[(i / 96) * 100 + (i % 96)] = fw2[i];
    for (int i = tid; i < 576; i += 512) w2s[i] = at_w2[i];

    int qb = blockIdx.x * QT;
    for (int e = tid; e < QT * 96; e += 512) {
        int q = e / 96, c = e % 96, gq = qb + q;
        float val;
        if (c < 3) val = img_xy[gq * 3 + c];
        else if (c < 11) val = ft_xy[gq * 8 + (c - 3)];
        else if (c < 69) {
            int i0 = g_idx[gq];
            int i1 = i0 + NUMVV; if (i1 >= NVV) i1 -= NVV;
            if (c < 22)      val = g_vf[i0 * 29 + (c - 11)]      * vvis[i0];
            else if (c < 33) val = g_vf[i1 * 29 + (c - 22)]      * vvis[i1];
            else if (c < 51) val = g_vf[i0 * 29 + 11 + (c - 33)] * vvis[i0];
            else             val = g_vf[i1 * 29 + 11 + (c - 51)] * vvis[i1];
        }
        else if (c < 93) val = latent[gq * 24 + (c - 69)];
        else if (c == 93) val = qvis[gq];
        else {
            int i0 = g_idx[gq];
            if (c == 94) val = vvis[i0];
            else { int i1 = i0 + NUMVV; if (i1 >= NVV) i1 -= NVV; val = vvis[i1]; }
        }
        Ys[q * 100 + c] = val;
    }
    __syncthreads();

    gemm_relu2(Ys, uW1, Hs, tid);           // h1 = relu(at_w1 @ y)
    __syncthreads();

    for (int e = tid; e < QT * 6; e += 512) {   // at = sigmoid(at_w2 @ h1)
        int q = e / 6, o = e % 6;
        const float4* wp = (const float4*)(w2s + o * 96);
        const float4* hp = (const float4*)(Hs + q * 100);
        float s = 0.f;
#pragma unroll
        for (int k = 0; k < 24; k++) {
            float4 a = wp[k], b = hp[k];
            s += a.x*b.x + a.y*b.y + a.z*b.z + a.w*b.w;
        }
        ATs[e] = 1.f / (1.f + expf(-s));
    }
    __syncthreads();

    for (int e = tid; e < QT * 96; e += 512) {  // y2: scale sections
        int q = e / 96, c = e % 96;
        int s = (c < 11) ? 0 : (c < 22) ? 1 : (c < 33) ? 2 : (c < 51) ? 3 : (c < 69) ? 4 : (c < 93) ? 5 : -1;
        if (s >= 0) Ys[q * 100 + c] *= ATs[q * 6 + s];
    }
    __syncthreads();

    gemm_relu2(Ys, uF1, Hs, tid);           // h2 = relu(fconv_w1 @ y2)
    __syncthreads();

    for (int e = tid; e < QT * 40; e += 512) {  // out = fconv_w2 @ h2
        int q = e / 40, o = e % 40;
        const float4* wp = (const float4*)(f2s + o * 100);
        const float4* hp = (const float4*)(Hs + q * 100);
        float s = 0.f;
#pragma unroll
        for (int k = 0; k < 24; k++) {
            float4 a = wp[k], b = hp[k];
            s += a.x*b.x + a.y*b.y + a.z*b.z + a.w*b.w;
        }
        out[(size_t)(qb + q) * 40 + o] = s;
    }
}

extern "C" void kernel_launch(void* const* d_in, const int* in_sizes, int n_in,
                              void* d_out, int out_size)
{
    const float* vert_xy = (const float*)d_in[0];
    const float* ft1     = (const float*)d_in[1];
    const float* ft_xy   = (const float*)d_in[2];
    const float* vert    = (const float*)d_in[3];
    const float* v       = (const float*)d_in[4];
    const float* vvis    = (const float*)d_in[5];
    const float* qvis    = (const float*)d_in[6];
    const float* img_xy  = (const float*)d_in[7];
    const float* img     = (const float*)d_in[8];
    const float* latent  = (const float*)d_in[9];
    const float* fw1     = (const float*)d_in[10];
    const float* fw2     = (const float*)d_in[11];
    const float* at_w1   = (const float*)d_in[12];
    const float* at_w2   = (const float*)d_in[13];
    const float* gt_w1   = (const float*)d_in[14];
    const float* gt_g1   = (const float*)d_in[15];
    const float* gt_b1   = (const float*)d_in[16];
    const float* gt_w2   = (const float*)d_in[17];
    const float* gt_g2   = (const float*)d_in[18];
    const float* gt_b2   = (const float*)d_in[19];
    const float* c3_w1   = (const float*)d_in[20];
    const float* c3_g1   = (const float*)d_in[21];
    const float* c3_b1   = (const float*)d_in[22];
    const float* c3_w2   = (const float*)d_in[23];
    const float* c3_g2   = (const float*)d_in[24];
    const float* c3_b2   = (const float*)d_in[25];
    const float* c4_w1   = (const float*)d_in[26];
    const float* c4_g1   = (const float*)d_in[27];
    const float* c4_b1   = (const float*)d_in[28];
    const float* c4_w2   = (const float*)d_in[29];
    const float* c4_g2   = (const float*)d_in[30];
    const float* c4_b2   = (const float*)d_in[31];
    float* out = (float*)d_out;

    float *A21, *A42, *B21, *B42, *meanA, *rstdA, *meanB, *rstdB, *gf, *H779, *vf;
    int* idx;
    cudaGetSymbolAddress((void**)&A21,   g_A21);
    cudaGetSymbolAddress((void**)&A42,   g_A42);
    cudaGetSymbolAddress((void**)&B21,   g_B21);
    cudaGetSymbolAddress((void**)&B42,   g_B42);
    cudaGetSymbolAddress((void**)&meanA, g_meanA);
    cudaGetSymbolAddress((void**)&rstdA, g_rstdA);
    cudaGetSymbolAddress((void**)&meanB, g_meanB);
    cudaGetSymbolAddress((void**)&rstdB, g_rstdB);
    cudaGetSymbolAddress((void**)&gf,    g_gf);
    cudaGetSymbolAddress((void**)&H779,  g_H779);
    cudaGetSymbolAddress((void**)&vf,    g_vf);
    cudaGetSymbolAddress((void**)&idx,   g_idx);

    static bool init_done = false;
    static cudaStream_t s2, s3;
    static cudaEvent_t evFork, evJ2, evJ3;
    if (!init_done) {
        cudaStreamCreateWithFlags(&s2, cudaStreamNonBlocking);
        cudaStreamCreateWithFlags(&s3, cudaStreamNonBlocking);
        cudaEventCreateWithFlags(&evFork, cudaEventDisableTiming);
        cudaEventCreateWithFlags(&evJ2, cudaEventDisableTiming);
        cudaEventCreateWithFlags(&evJ3, cudaEventDisableTiming);
        cudaFuncSetAttribute(gt2_k, cudaFuncAttributeMaxDynamicSharedMemorySize, (779*19 + 256*18) * 4);
        cudaFuncSetAttribute(fused_main, cudaFuncAttributeMaxDynamicSharedMemorySize, FM_SMEM);
        init_done = true;
    }

    cudaEventRecord(evFork, 0);
    cudaStreamWaitEvent(s2, evFork, 0);
    cudaStreamWaitEvent(s3, evFork, 0);

    // s2: nearest vertex (independent of everything else)
    argmin_k<<<NQV / 256, 256, 0, s2>>>(v, vert, idx);
    cudaEventRecord(evJ2, s2);

    // s3: vertex sampling + c3 branch (ft1 64x64)
    feat_vert_k<<<(NVV + 255) / 256, 256, 0, s3>>>(vert_xy, img, ft1, vf);
    conv3x3<8, 21, 64, false><<<dim3(4, 8), 128, 8*180*4 + 8*9*12*8, s3>>>(
        ft1, c3_w1, B21, nullptr, nullptr, nullptr, nullptr);
    chan_stats<<<21, 256, 0, s3>>>(B21, 4096, meanB, rstdB);
    conv3x3<21, 42, 64, true><<<dim3(4, 8), 128, 21*180*4 + 21*9*22*8, s3>>>(
        B21, c3_w2, B42, meanB, rstdB, c3_g1, c3_b1);
    chan_stats<<<42, 256, 0, s3>>>(B42, 4096, meanB, rstdB);
    apool<<<dim3(9, 42), 256, 0, s3>>>(B42, 64, meanB, rstdB, c3_g2, c3_b2, gf, 9);
    cudaEventRecord(evJ3, s3);

    // main: c4 branch (img_fmap 256x256)
    conv3x3<3, 21, 256, false><<<dim3(16, 32), 128, 3*180*4 + 3*9*12*8>>>(
        img, c4_w1, A21, nullptr, nullptr, nullptr, nullptr);
    chan_stats<<<21, 256>>>(A21, 65536, meanA, rstdA);
    conv3x3<21, 42, 256, true><<<dim3(16, 32), 128, 21*180*4 + 21*9*22*8>>>(
        A21, c4_w2, A42, meanA, rstdA, c4_g1, c4_b1);
    chan_stats<<<42, 256>>>(A42, 65536, meanA, rstdA);
    apool<<<dim3(9, 42), 256>>>(A42, 256, meanA, rstdA, c4_g2, c4_b2, gf, 0);

    // join c3 branch, then graph convs
    cudaStreamWaitEvent(0, evJ3, 0);
    gt1_k<<<NUMVV, 32>>>(gf, gt_w1, gt_g1, gt_b1, H779);
    gt2_k<<<NVV, 256, (779*19 + 256*18) * 4>>>(H779, gt_w2, gt_g2, gt_b2, vf);

    // join argmin, then fused MLP
    cudaStreamWaitEvent(0, evJ2, 0);
    fused_main<<<NQV / QT, 512, FM_SMEM>>>(img_xy, ft_xy, latent, qvis, vvis,
                                           at_w1, at_w2, fw1, fw2, out);
}